// round 17
// baseline (speedup 1.0000x reference)
#include <cuda_runtime.h>
#include <cstdint>

// Problem constants
constexpr int KC = 5, PC = 2, BC = 2, NC = 8, HC = 512, WC = 512;

// BARRIER-FREE variant: no shared memory, no cp.async, no __syncthreads.
// Each thread gathers its 5-row x 12-col frame window directly from global
// memory (3 aligned predicated LDG.128 per row; L1/L2 hits after first
// touch -- frames is 16.8MB, fully L2-resident, ~40x line reuse), THEN runs
// the pure 25x LDG.128 __ldcs core burst. Full-width 4x512 tiles, persistent
// CTAs with static strided schedule, __stcs streaming store.
constexpr int TH = 4;
constexpr int NT = 512;              // threads per CTA
constexpr int TILES_Y = HC / TH;     // 128 row-tiles
constexpr int N_TILES = TILES_Y * BC * NC;   // 2048
constexpr int GRID = 304;            // 152 SM x 2 CTAs, persistent

__global__ __launch_bounds__(NT, 2)
void kconv_kernel(const float* __restrict__ frames,
                  const float* __restrict__ core,
                  const float* __restrict__ Wt,
                  float* __restrict__ out)
{
    const size_t plane = (size_t)HC * WC;

    // Thread -> output mapping: 4 rows x 128 float4-groups per tile.
    const int row = threadIdx.x >> 7;            // 0..3
    const int xx  = (threadIdx.x & 127) << 2;    // 0..508

    // Column-chunk predicates are tile-invariant (depend only on xx)
    const bool okL = (xx >= 4);                  // cols xx-4..xx-1 in image
    const bool okR = (xx + 4 < WC);              // cols xx+4..xx+7 in image

    for (int t = blockIdx.x; t < N_TILES; t += GRID) {
        const int ty = (t & (TILES_Y - 1)) * TH;
        const int z  = t >> 7;                   // b*N + n
        const int gy = ty + row;
        const size_t pix = (size_t)gy * WC + xx;

        const float* fbase = frames + (size_t)z * plane;
        const float* cbase = core   + (size_t)z * (KC * KC) * plane;
        const float* wbase = Wt     + (size_t)z * plane;
        float*       obase = out    + (size_t)z * plane;

        // W: read-once stream, issue early
        const float4 wv = __ldcs(reinterpret_cast<const float4*>(wbase + pix));

        // ---- gather the 5x12 frame window directly from global ----
        // w[i][c] = frames[gy+i-2][xx-4+c], zero outside the image.
        // Row i uses cols xx-2+j+m (j 0..4, m 0..3) -> w indices 2..10.
        float w[KC][12];
        #pragma unroll
        for (int i = 0; i < KC; ++i) {
            const int ry = gy + i - PC;
            const bool okRow = (unsigned)ry < (unsigned)HC;
            const float* rp = fbase + (size_t)(okRow ? ry : 0) * WC;

            float4 c0 = make_float4(0.f, 0.f, 0.f, 0.f);
            float4 c1 = make_float4(0.f, 0.f, 0.f, 0.f);
            float4 c2 = make_float4(0.f, 0.f, 0.f, 0.f);
            if (okRow) {
                if (okL) c0 = __ldg(reinterpret_cast<const float4*>(rp + xx - 4));
                c1 = __ldg(reinterpret_cast<const float4*>(rp + xx));
                if (okR) c2 = __ldg(reinterpret_cast<const float4*>(rp + xx + 4));
            }
            w[i][0] = c0.x; w[i][1] = c0.y; w[i][2]  = c0.z; w[i][3]  = c0.w;
            w[i][4] = c1.x; w[i][5] = c1.y; w[i][6]  = c1.z; w[i][7]  = c1.w;
            w[i][8] = c2.x; w[i][9] = c2.y; w[i][10] = c2.z; w[i][11] = c2.w;
        }

        // ---- pure LDG->FMA core burst (25 contiguous-8KB plane streams) ----
        float acc0 = 0.f, acc1 = 0.f, acc2 = 0.f, acc3 = 0.f;
        #pragma unroll
        for (int i = 0; i < KC; ++i) {
            #pragma unroll
            for (int j = 0; j < KC; ++j) {
                const int k = i * KC + j;
                const float4 cv = __ldcs(
                    reinterpret_cast<const float4*>(cbase + (size_t)k * plane + pix));
                // output col xx+m uses frame col xx+m+j-2 = w index j+m+2
                acc0 = fmaf(cv.x, w[i][j + 2], acc0);
                acc1 = fmaf(cv.y, w[i][j + 3], acc1);
                acc2 = fmaf(cv.z, w[i][j + 4], acc2);
                acc3 = fmaf(cv.w, w[i][j + 5], acc3);
            }
        }

        float4 o;
        o.x = acc0 * wv.x;
        o.y = acc1 * wv.y;
        o.z = acc2 * wv.z;
        o.w = acc3 * wv.w;
        __stcs(reinterpret_cast<float4*>(obase + pix), o);
    }
}

extern "C" void kernel_launch(void* const* d_in, const int* in_sizes, int n_in,
                              void* d_out, int out_size)
{
    const float* frames = (const float*)d_in[0];
    const float* core   = (const float*)d_in[1];
    const float* Wt     = (const float*)d_in[2];
    float* out          = (float*)d_out;

    kconv_kernel<<<GRID, NT>>>(frames, core, Wt, out);
}